// round 15
// baseline (speedup 1.0000x reference)
#include <cuda_runtime.h>
#include <cuda_fp16.h>
#include <cstdint>

#define Bsz 2
#define Cc  256
#define Nn  4096
#define Hh  8
#define Gg  8
#define CPG 32
#define EPSv 1e-5f
// log2(e)/sqrt(32)
#define CEXP 0.25503486f

__device__ float  g_scale[Bsz * Cc];
__device__ float  g_shift[Bsz * Cc];
__device__ float  g_part[Bsz * Gg * 8 * 2];
__device__ __half g_XNh[Bsz * Cc * Nn];
__device__ __half g_Wh[4 * Cc * Cc];
__device__ __half g_Qh[Bsz * Cc * Nn];
__device__ __half g_Kh[Bsz * Cc * Nn];
__device__ __half g_Vh[Bsz * Cc * Nn];
__device__ __half g_AOh[Bsz * Cc * Nn];

// attention smem (halves): sK[4][32][136], sV[4][32][136], sQ[32][520]
#define KV_BUF   (32 * 136)
#define SK_OFF   0
#define SV_OFF   (4 * KV_BUF)
#define SQ_OFF   (8 * KV_BUF)
#define SQ_STRIDE 520
#define ATTN_SMEM_BYTES ((8 * KV_BUF + 32 * 520) * 2)

// ---------------------------------------------------------------------------
// helpers
// ---------------------------------------------------------------------------
__device__ __forceinline__ uint32_t smem_u32(const void* p) {
    uint32_t a;
    asm("{ .reg .u64 t; cvta.to.shared.u64 t, %1; cvt.u32.u64 %0, t; }"
        : "=r"(a) : "l"(p));
    return a;
}
__device__ __forceinline__ void ldsm_x4(uint32_t r[4], uint32_t a) {
    asm volatile("ldmatrix.sync.aligned.m8n8.x4.shared.b16 {%0,%1,%2,%3}, [%4];"
                 : "=r"(r[0]), "=r"(r[1]), "=r"(r[2]), "=r"(r[3]) : "r"(a));
}
__device__ __forceinline__ void ldsm_x4t(uint32_t r[4], uint32_t a) {
    asm volatile("ldmatrix.sync.aligned.m8n8.x4.trans.shared.b16 {%0,%1,%2,%3}, [%4];"
                 : "=r"(r[0]), "=r"(r[1]), "=r"(r[2]), "=r"(r[3]) : "r"(a));
}
__device__ __forceinline__ void mma16816(float c[4], const uint32_t a[4],
                                         const uint32_t b0, const uint32_t b1) {
    asm volatile(
        "mma.sync.aligned.m16n8k16.row.col.f32.f16.f16.f32 "
        "{%0,%1,%2,%3}, {%4,%5,%6,%7}, {%8,%9}, {%0,%1,%2,%3};"
        : "+f"(c[0]), "+f"(c[1]), "+f"(c[2]), "+f"(c[3])
        : "r"(a[0]), "r"(a[1]), "r"(a[2]), "r"(a[3]), "r"(b0), "r"(b1));
}
__device__ __forceinline__ uint32_t exp2h2(float lo, float hi) {
    uint32_t d;
    asm("{ .reg .b32 t;\n\t"
        "cvt.rn.f16x2.f32 t, %2, %1;\n\t"
        "ex2.approx.f16x2 %0, t; }"
        : "=r"(d) : "f"(lo), "f"(hi));
    return d;
}
__device__ __forceinline__ uint32_t packh2(float a, float b) {
    __half2 h = __floats2half2_rn(a, b);
    return *(uint32_t*)&h;
}
__device__ __forceinline__ void cp16(uint32_t dst, const void* src) {
    asm volatile("cp.async.cg.shared.global [%0], [%1], 16;"
                 :: "r"(dst), "l"(src) : "memory");
}
#define CP_COMMIT() asm volatile("cp.async.commit_group;" ::: "memory")
#define CP_WAIT2()  asm volatile("cp.async.wait_group 2;" ::: "memory")
#define CP_WAIT1()  asm volatile("cp.async.wait_group 1;" ::: "memory")
#define CP_WAIT0()  asm volatile("cp.async.wait_group 0;" ::: "memory")

// ---------------------------------------------------------------------------
// Kernel 1: merged prep — blocks 0..255 convert weights to fp16,
// blocks 256..383 compute GroupNorm partial sums.
// ---------------------------------------------------------------------------
__global__ void prep_kernel(const float* __restrict__ x,
                            const float* __restrict__ w0, const float* __restrict__ w1,
                            const float* __restrict__ w2, const float* __restrict__ w3) {
    if (blockIdx.x < 256) {
        int i = blockIdx.x * 256 + threadIdx.x;
        int sel = i >> 14;
        const float* w = (sel == 0) ? w0 : (sel == 1) ? w1 : (sel == 2) ? w2 : w3;
        float4 v = ((const float4*)w)[i & 16383];
        uint2 u;
        u.x = packh2(v.x, v.y);
        u.y = packh2(v.z, v.w);
        ((uint2*)g_Wh)[i] = u;
        return;
    }
    int blk = blockIdx.x - 256;
    int bg = blk >> 3, slice = blk & 7;
    int b = bg / Gg, g = bg % Gg;
    const float4* xp = (const float4*)(x + ((size_t)b * Cc + g * CPG) * Nn)
                     + slice * (CPG * Nn / 4 / 8);
    const int n4 = CPG * Nn / 4 / 8;

    float s = 0.f, ss = 0.f;
    for (int i = threadIdx.x; i < n4; i += 256) {
        float4 v = xp[i];
        s  += v.x + v.y + v.z + v.w;
        ss += v.x * v.x + v.y * v.y + v.z * v.z + v.w * v.w;
    }
    __shared__ float rs[8], rss[8];
    #pragma unroll
    for (int off = 16; off; off >>= 1) {
        s  += __shfl_down_sync(0xffffffffu, s, off);
        ss += __shfl_down_sync(0xffffffffu, ss, off);
    }
    int lane = threadIdx.x & 31, wid = threadIdx.x >> 5;
    if (lane == 0) { rs[wid] = s; rss[wid] = ss; }
    __syncthreads();
    if (threadIdx.x < 8) {
        s = rs[threadIdx.x]; ss = rss[threadIdx.x];
        #pragma unroll
        for (int off = 4; off; off >>= 1) {
            s  += __shfl_down_sync(0xffu, s, off);
            ss += __shfl_down_sync(0xffu, ss, off);
        }
        if (threadIdx.x == 0) {
            g_part[(bg * 8 + slice) * 2 + 0] = s;
            g_part[(bg * 8 + slice) * 2 + 1] = ss;
        }
    }
}

// ---------------------------------------------------------------------------
// Kernel 1b: finalize
// ---------------------------------------------------------------------------
__global__ void gn_fin_kernel(const float* __restrict__ w,
                              const float* __restrict__ bias) {
    int t = threadIdx.x;
    int c = t & 255;
    int bg = t >> 5;
    float s = 0.f, ss = 0.f;
    #pragma unroll
    for (int i = 0; i < 8; i++) {
        s  += g_part[(bg * 8 + i) * 2 + 0];
        ss += g_part[(bg * 8 + i) * 2 + 1];
    }
    const float inv = 1.f / (float)(CPG * Nn);
    float mu = s * inv;
    float var = ss * inv - mu * mu;
    float rstd = rsqrtf(var + EPSv);
    float sc = rstd * w[c];
    g_scale[t] = sc;
    g_shift[t] = bias[c] - mu * sc;
}

// ---------------------------------------------------------------------------
// Kernel 2: normalize -> fp16
// ---------------------------------------------------------------------------
__global__ void normalize_kernel(const float* __restrict__ x) {
    int base = blockIdx.x * 512 + threadIdx.x;
    #pragma unroll
    for (int u = 0; u < 2; u++) {
        int i = base + u * 256;
        int bc = i >> 10;
        float sc = g_scale[bc], sh = g_shift[bc];
        float4 v = ((const float4*)x)[i];
        uint2 o;
        o.x = packh2(fmaf(v.x, sc, sh), fmaf(v.y, sc, sh));
        o.y = packh2(fmaf(v.z, sc, sh), fmaf(v.w, sc, sh));
        ((uint2*)g_XNh)[i] = o;
    }
}

// ---------------------------------------------------------------------------
// Kernel 3: stacked QKV GEMM (M=768). BM=128 BN=128 BK=32, 2-stage cp.async.
// ---------------------------------------------------------------------------
__global__ void __launch_bounds__(256)
gemm_qkv(const __half* __restrict__ Wp,
         const float* __restrict__ bq, const float* __restrict__ bk,
         const float* __restrict__ bv) {
    __shared__ __align__(16) __half sA[2][128][40];
    __shared__ __align__(16) __half sB[2][32][136];

    int bz = blockIdx.z;
    const __half* X = g_XNh + (size_t)bz * Cc * Nn;
    int n0 = blockIdx.x * 128;
    int mg = blockIdx.y * 128;
    int which = mg >> 8;
    int m0 = mg & 255;
    int tid = threadIdx.x, lane = tid & 31, wid = tid >> 5;
    int wm = wid & 1, wn = wid >> 1;
    int g = lane >> 2, tg = lane & 3;
    int r7 = lane & 7, sel = lane >> 3, r15 = lane & 15, hi8 = lane >> 4;

    float c[4][4][4] = {};

    auto issue = [&](int kt, int buf) {
        int k0 = kt * 32;
        #pragma unroll
        for (int i = 0; i < 2; i++) {
            int idx = tid + i * 256;
            int arow = idx >> 2, acol = (idx & 3) << 3;
            cp16(smem_u32(&sA[buf][arow][acol]),
                 Wp + (size_t)(mg + arow) * Cc + k0 + acol);
            int brow = idx >> 4, bcc = (idx & 15) << 3;
            cp16(smem_u32(&sB[buf][brow & 31][bcc]),
                 X + (size_t)(k0 + (brow & 31)) * Nn + n0 + bcc);
        }
    };

    issue(0, 0); CP_COMMIT();

    for (int kt = 0; kt < 8; kt++) {
        int cur = kt & 1;
        if (kt + 1 < 8) { issue(kt + 1, cur ^ 1); CP_COMMIT(); CP_WAIT1(); }
        else            { CP_WAIT0(); }
        __syncthreads();

        #pragma unroll
        for (int ks = 0; ks < 2; ks++) {
            uint32_t a[4][4], bf[2][4];
            #pragma unroll
            for (int mt = 0; mt < 4; mt++)
                ldsm_x4(a[mt],
                        smem_u32(&sA[cur][wm * 64 + mt * 16 + (sel & 1) * 8 + r7]
                                        [ks * 16 + (sel >> 1) * 8]));
            #pragma unroll
            for (int jp = 0; jp < 2; jp++)
                ldsm_x4t(bf[jp],
                         smem_u32(&sB[cur][ks * 16 + r15][wn * 32 + jp * 16 + hi8 * 8]));
            #pragma unroll
            for (int mt = 0; mt < 4; mt++)
                #pragma unroll
                for (int jp = 0; jp < 2; jp++) {
                    mma16816(c[mt][jp * 2 + 0], a[mt], bf[jp][0], bf[jp][1]);
                    mma16816(c[mt][jp * 2 + 1], a[mt], bf[jp][2], bf[jp][3]);
                }
        }
        __syncthreads();
    }

    __half* outp = ((which == 0) ? g_Qh : (which == 1) ? g_Kh : g_Vh)
                 + (size_t)bz * Cc * Nn;
    const float* bp = (which == 0) ? bq : (which == 1) ? bk : bv;
    #pragma unroll
    for (int mt = 0; mt < 4; mt++) {
        int m = m0 + wm * 64 + mt * 16 + g;
        float b0 = bp[m], b1 = bp[m + 8];
        #pragma unroll
        for (int jt = 0; jt < 4; jt++) {
            int n = n0 + wn * 32 + jt * 8 + 2 * tg;
            *(__half2*)(outp + (size_t)m * Nn + n) =
                __floats2half2_rn(c[mt][jt][0] + b0, c[mt][jt][1] + b0);
            *(__half2*)(outp + (size_t)(m + 8) * Nn + n) =
                __floats2half2_rn(c[mt][jt][2] + b1, c[mt][jt][3] + b1);
        }
    }
}

// ---------------------------------------------------------------------------
// Kernel 5: output projection GEMM + residual, fp32 out.
// ---------------------------------------------------------------------------
__global__ void __launch_bounds__(256)
gemm_o(const __half* __restrict__ Wp, const float* __restrict__ bias,
       const float* __restrict__ resid, float* __restrict__ Out) {
    __shared__ __align__(16) __half sA[2][128][40];
    __shared__ __align__(16) __half sB[2][32][136];

    int bz = blockIdx.z;
    const __half* X = g_AOh + (size_t)bz * Cc * Nn;
    int n0 = blockIdx.x * 128, m0 = blockIdx.y * 128;
    int tid = threadIdx.x, lane = tid & 31, wid = tid >> 5;
    int wm = wid & 1, wn = wid >> 1;
    int g = lane >> 2, tg = lane & 3;
    int r7 = lane & 7, sel = lane >> 3, r15 = lane & 15, hi8 = lane >> 4;

    float c[4][4][4] = {};

    auto issue = [&](int kt, int buf) {
        int k0 = kt * 32;
        #pragma unroll
        for (int i = 0; i < 2; i++) {
            int idx = tid + i * 256;
            int arow = idx >> 2, acol = (idx & 3) << 3;
            cp16(smem_u32(&sA[buf][arow][acol]),
                 Wp + (size_t)(m0 + arow) * Cc + k0 + acol);
            int brow = idx >> 4, bcc = (idx & 15) << 3;
            cp16(smem_u32(&sB[buf][brow & 31][bcc]),
                 X + (size_t)(k0 + (brow & 31)) * Nn + n0 + bcc);
        }
    };

    issue(0, 0); CP_COMMIT();

    for (int kt = 0; kt < 8; kt++) {
        int cur = kt & 1;
        if (kt + 1 < 8) { issue(kt + 1, cur ^ 1); CP_COMMIT(); CP_WAIT1(); }
        else            { CP_WAIT0(); }
        __syncthreads();

        #pragma unroll
        for (int ks = 0; ks < 2; ks++) {
            uint32_t a[4][4], bf[2][4];
            #pragma unroll
            for (int mt = 0; mt < 4; mt++)
                ldsm_x4(a[mt],
                        smem_u32(&sA[cur][wm * 64 + mt * 16 + (sel & 1) * 8 + r7]
                                        [ks * 16 + (sel >> 1) * 8]));
            #pragma unroll
            for (int jp = 0; jp < 2; jp++)
                ldsm_x4t(bf[jp],
                         smem_u32(&sB[cur][ks * 16 + r15][wn * 32 + jp * 16 + hi8 * 8]));
            #pragma unroll
            for (int mt = 0; mt < 4; mt++)
                #pragma unroll
                for (int jp = 0; jp < 2; jp++) {
                    mma16816(c[mt][jp * 2 + 0], a[mt], bf[jp][0], bf[jp][1]);
                    mma16816(c[mt][jp * 2 + 1], a[mt], bf[jp][2], bf[jp][3]);
                }
        }
        __syncthreads();
    }

    #pragma unroll
    for (int mt = 0; mt < 4; mt++) {
        int m = m0 + wm * 64 + mt * 16 + g;
        float b0 = bias[m], b1 = bias[m + 8];
        #pragma unroll
        for (int jt = 0; jt < 4; jt++) {
            int n = n0 + wn * 32 + jt * 8 + 2 * tg;
            size_t o0 = ((size_t)bz * Cc + m) * Nn + n;
            size_t o1 = ((size_t)bz * Cc + m + 8) * Nn + n;
            float2 r0 = *(const float2*)(resid + o0);
            float2 r1 = *(const float2*)(resid + o1);
            *(float2*)(Out + o0) = make_float2(c[mt][jt][0] + b0 + r0.x,
                                               c[mt][jt][1] + b0 + r0.y);
            *(float2*)(Out + o1) = make_float2(c[mt][jt][2] + b1 + r1.x,
                                               c[mt][jt][3] + b1 + r1.y);
        }
    }
}

// ---------------------------------------------------------------------------
// Kernel 4: HMMA flash attention. 512 q/block, grid 128 = 1 balanced wave.
// Bc=128 keys/tile (32 iterations), 4-stage cp.async ring, ONE barrier/iter.
// Rowsums now on the fma/alu pipes (hadd2 + fp32 accumulate): tensor pipe
// runs only QK + PV (256 MMA/iter vs 288) — justified because at 2 warps/SMSP
// tensor demand (~4030 cyc/iter) >> issue demand (~1000), unlike R11's config.
// ---------------------------------------------------------------------------
extern __shared__ __half s_attn[];

__global__ void __launch_bounds__(256, 1)
attn_kernel() {
    __half* sK = s_attn + SK_OFF;   // [4][32][136]
    __half* sV = s_attn + SV_OFF;   // [4][32][136]
    __half* sQ = s_attn + SQ_OFF;   // [32][520]

    int tid = threadIdx.x, lane = tid & 31, wid = tid >> 5;
    int b = blockIdx.z, h = blockIdx.y;
    int q0 = blockIdx.x * 512;
    size_t base = ((size_t)b * Cc + h * 32) * Nn;
    const __half* Qg = g_Qh + base;
    const __half* Kg = g_Kh + base;
    const __half* Vg = g_Vh + base;
    int g = lane >> 2, tg = lane & 3;
    int r7 = lane & 7, sel = lane >> 3, r15 = lane & 15, hi8 = lane >> 4;

    auto kv_off = [](int buf, int row, int col) {
        return buf * KV_BUF + row * 136 + col;
    };
    auto issue = [&](int t, int buf) {
        int row = tid >> 3;
        #pragma unroll
        for (int i = 0; i < 2; i++) {
            int cc = ((tid & 7) << 3) + i * 64;
            size_t off = (size_t)row * Nn + t * 128 + cc;
            cp16(smem_u32(sK + kv_off(buf, row, cc)), Kg + off);
            cp16(smem_u32(sV + kv_off(buf, row, cc)), Vg + off);
        }
    };

    issue(0, 0); CP_COMMIT();
    issue(1, 1); CP_COMMIT();

    // Q staging: 32 d-rows x 512 queries
    #pragma unroll
    for (int i = 0; i < 8; i++) {
        int idx = tid + i * 256;
        int row = idx >> 6, cc = (idx & 63) << 3;
        *(uint4*)(sQ + row * SQ_STRIDE + cc) =
            *(const uint4*)(Qg + (size_t)row * Nn + q0 + cc);
    }
    __syncthreads();
    uint32_t qa[4][2][4];
    const __half2 cs2 = __float2half2_rn(CEXP);
    #pragma unroll
    for (int mt = 0; mt < 4; mt++)
        #pragma unroll
        for (int s = 0; s < 2; s++) {
            ldsm_x4t(qa[mt][s],
                     smem_u32(sQ + (s * 16 + (sel >> 1) * 8 + r7) * SQ_STRIDE
                                 + wid * 64 + mt * 16 + (sel & 1) * 8));
            #pragma unroll
            for (int i = 0; i < 4; i++) {
                __half2 t2 = __hmul2(*(__half2*)&qa[mt][s][i], cs2);
                qa[mt][s][i] = *(uint32_t*)&t2;
            }
        }

    float oc[4][4][4] = {};
    float rs[4][2] = {};
    const int NT = Nn / 128;   // 32

    for (int t = 0; t < NT; t++) {
        int cur = t & 3;
        if (t + 2 < NT) { issue(t + 2, (t + 2) & 3); CP_COMMIT(); CP_WAIT2(); }
        else if (t + 1 < NT) { CP_WAIT1(); }
        else                 { CP_WAIT0(); }
        __syncthreads();   // the ONLY barrier in the iteration

        #pragma unroll
        for (int jp = 0; jp < 8; jp++) {
            uint32_t kf[2][4];
            #pragma unroll
            for (int s = 0; s < 2; s++)
                ldsm_x4t(kf[s], smem_u32(sK + kv_off(cur, s * 16 + r15,
                                                     jp * 16 + hi8 * 8)));
            uint32_t pa[4][4];
            #pragma unroll
            for (int mt = 0; mt < 4; mt++)
                #pragma unroll
                for (int j2 = 0; j2 < 2; j2++) {
                    float sc[4] = {0.f, 0.f, 0.f, 0.f};
                    mma16816(sc, qa[mt][0], kf[0][j2 * 2], kf[0][j2 * 2 + 1]);
                    mma16816(sc, qa[mt][1], kf[1][j2 * 2], kf[1][j2 * 2 + 1]);
                    pa[mt][j2 * 2 + 0] = exp2h2(sc[0], sc[1]);
                    pa[mt][j2 * 2 + 1] = exp2h2(sc[2], sc[3]);
                }
            // row sums on the fma pipe (pa[0],pa[2] = row g; pa[1],pa[3] = row g+8)
            #pragma unroll
            for (int mt = 0; mt < 4; mt++) {
                __half2 s0 = __hadd2(*(__half2*)&pa[mt][0], *(__half2*)&pa[mt][2]);
                __half2 s1 = __hadd2(*(__half2*)&pa[mt][1], *(__half2*)&pa[mt][3]);
                float2 f0 = __half22float2(s0);
                float2 f1 = __half22float2(s1);
                rs[mt][0] += f0.x + f0.y;
                rs[mt][1] += f1.x + f1.y;
            }
            // O += P V^T
            #pragma unroll
            for (int dnp = 0; dnp < 2; dnp++) {
                uint32_t vf[4];
                ldsm_x4(vf, smem_u32(sV + kv_off(cur, dnp * 16 + hi8 * 8 + r7,
                                                 jp * 16 + ((lane >> 3) & 1) * 8)));
                #pragma unroll
                for (int mt = 0; mt < 4; mt++) {
                    mma16816(oc[mt][dnp * 2],     pa[mt], vf[0], vf[1]);
                    mma16816(oc[mt][dnp * 2 + 1], pa[mt], vf[2], vf[3]);
                }
            }
        }
    }

    __syncthreads();
    // reduce row sums across the 4 tg lanes, normalize, stage O, store
    #pragma unroll
    for (int mt = 0; mt < 4; mt++) {
        #pragma unroll
        for (int r = 0; r < 2; r++) {
            rs[mt][r] += __shfl_xor_sync(0xffffffffu, rs[mt][r], 1);
            rs[mt][r] += __shfl_xor_sync(0xffffffffu, rs[mt][r], 2);
        }
        float inv0 = 1.f / rs[mt][0], inv1 = 1.f / rs[mt][1];
        int qc = wid * 64 + mt * 16;
        #pragma unroll
        for (int dn = 0; dn < 4; dn++) {
            int d0 = dn * 8 + 2 * tg;
            sQ[d0 * SQ_STRIDE + qc + g]           = __float2half(oc[mt][dn][0] * inv0);
            sQ[(d0 + 1) * SQ_STRIDE + qc + g]     = __float2half(oc[mt][dn][1] * inv0);
            sQ[d0 * SQ_STRIDE + qc + g + 8]       = __float2half(oc[mt][dn][2] * inv1);
            sQ[(d0 + 1) * SQ_STRIDE + qc + g + 8] = __float2half(oc[mt][dn][3] * inv1);
        }
    }
    __syncthreads();
    __half* AO = g_AOh + base;
    #pragma unroll
    for (int i = 0; i < 8; i++) {
        int idx = tid + i * 256;
        int row = idx >> 6, cc = (idx & 63) << 3;
        *(uint4*)(AO + (size_t)row * Nn + q0 + cc) =
            *(uint4*)(sQ + row * SQ_STRIDE + cc);
    }
}

// ---------------------------------------------------------------------------
// Launch
// ---------------------------------------------------------------------------
extern "C" void kernel_launch(void* const* d_in, const int* in_sizes, int n_in,
                              void* d_out, int out_size) {
    const float* x    = (const float*)d_in[0];
    const float* gn_w = (const float*)d_in[1];
    const float* gn_b = (const float*)d_in[2];
    const float* wq   = (const float*)d_in[3];
    const float* bq   = (const float*)d_in[4];
    const float* wk   = (const float*)d_in[5];
    const float* bk   = (const float*)d_in[6];
    const float* wv   = (const float*)d_in[7];
    const float* bv   = (const float*)d_in[8];
    const float* wo   = (const float*)d_in[9];
    const float* bo   = (const float*)d_in[10];
    float* out = (float*)d_out;

    __half* wh;
    cudaGetSymbolAddress((void**)&wh, g_Wh);

    static bool attr_set = false;
    if (!attr_set) {
        cudaFuncSetAttribute(attn_kernel,
                             cudaFuncAttributeMaxDynamicSharedMemorySize,
                             ATTN_SMEM_BYTES);
        attr_set = true;
    }

    prep_kernel<<<384, 256>>>(x, wq, wk, wv, wo);
    gn_fin_kernel<<<1, 512>>>(gn_w, gn_b);
    normalize_kernel<<<(Bsz * Cc * Nn / 4) / 512, 256>>>(x);

    gemm_qkv<<<dim3(Nn / 128, 6, Bsz), 256>>>(wh, bq, bk, bv);

    attn_kernel<<<dim3(Nn / 512, Hh, Bsz), 256, ATTN_SMEM_BYTES>>>();

    gemm_o<<<dim3(Nn / 128, Cc / 128, Bsz), 256>>>(wh + 3 * Cc * Cc, bo, x, out);
}

// round 16
// speedup vs baseline: 1.0125x; 1.0125x over previous
#include <cuda_runtime.h>
#include <cuda_fp16.h>
#include <cstdint>

#define Bsz 2
#define Cc  256
#define Nn  4096
#define Hh  8
#define Gg  8
#define CPG 32
#define EPSv 1e-5f
// log2(e)/sqrt(32)
#define CEXP 0.25503486f

__device__ float  g_scale[Bsz * Cc];
__device__ float  g_shift[Bsz * Cc];
__device__ float  g_part[Bsz * Gg * 8 * 2];
__device__ __half g_Wh[4 * Cc * Cc];
__device__ __half g_Qh[Bsz * Cc * Nn];
__device__ __half g_Kh[Bsz * Cc * Nn];
__device__ __half g_Vh[Bsz * Cc * Nn];
__device__ __half g_AOh[Bsz * Cc * Nn];

// attention smem (halves): sK[4][32][136], sV[4][32][136], sQ[32][520]
#define KV_BUF   (32 * 136)
#define SK_OFF   0
#define SV_OFF   (4 * KV_BUF)
#define SQ_OFF   (8 * KV_BUF)
#define SQ_STRIDE 520
#define ATTN_SMEM_BYTES ((8 * KV_BUF + 32 * 520) * 2)

// ---------------------------------------------------------------------------
// helpers
// ---------------------------------------------------------------------------
__device__ __forceinline__ uint32_t smem_u32(const void* p) {
    uint32_t a;
    asm("{ .reg .u64 t; cvta.to.shared.u64 t, %1; cvt.u32.u64 %0, t; }"
        : "=r"(a) : "l"(p));
    return a;
}
__device__ __forceinline__ void ldsm_x4(uint32_t r[4], uint32_t a) {
    asm volatile("ldmatrix.sync.aligned.m8n8.x4.shared.b16 {%0,%1,%2,%3}, [%4];"
                 : "=r"(r[0]), "=r"(r[1]), "=r"(r[2]), "=r"(r[3]) : "r"(a));
}
__device__ __forceinline__ void ldsm_x4t(uint32_t r[4], uint32_t a) {
    asm volatile("ldmatrix.sync.aligned.m8n8.x4.trans.shared.b16 {%0,%1,%2,%3}, [%4];"
                 : "=r"(r[0]), "=r"(r[1]), "=r"(r[2]), "=r"(r[3]) : "r"(a));
}
__device__ __forceinline__ void mma16816(float c[4], const uint32_t a[4],
                                         const uint32_t b0, const uint32_t b1) {
    asm volatile(
        "mma.sync.aligned.m16n8k16.row.col.f32.f16.f16.f32 "
        "{%0,%1,%2,%3}, {%4,%5,%6,%7}, {%8,%9}, {%0,%1,%2,%3};"
        : "+f"(c[0]), "+f"(c[1]), "+f"(c[2]), "+f"(c[3])
        : "r"(a[0]), "r"(a[1]), "r"(a[2]), "r"(a[3]), "r"(b0), "r"(b1));
}
__device__ __forceinline__ uint32_t exp2h2(float lo, float hi) {
    uint32_t d;
    asm("{ .reg .b32 t;\n\t"
        "cvt.rn.f16x2.f32 t, %2, %1;\n\t"
        "ex2.approx.f16x2 %0, t; }"
        : "=r"(d) : "f"(lo), "f"(hi));
    return d;
}
__device__ __forceinline__ uint32_t packh2(float a, float b) {
    __half2 h = __floats2half2_rn(a, b);
    return *(uint32_t*)&h;
}
__device__ __forceinline__ void cp16(uint32_t dst, const void* src) {
    asm volatile("cp.async.cg.shared.global [%0], [%1], 16;"
                 :: "r"(dst), "l"(src) : "memory");
}
#define CP_COMMIT() asm volatile("cp.async.commit_group;" ::: "memory")
#define CP_WAIT2()  asm volatile("cp.async.wait_group 2;" ::: "memory")
#define CP_WAIT1()  asm volatile("cp.async.wait_group 1;" ::: "memory")
#define CP_WAIT0()  asm volatile("cp.async.wait_group 0;" ::: "memory")

// ---------------------------------------------------------------------------
// Kernel 1: merged prep — blocks 0..255 convert weights to fp16,
// blocks 256..383 compute GroupNorm partial sums.
// ---------------------------------------------------------------------------
__global__ void prep_kernel(const float* __restrict__ x,
                            const float* __restrict__ w0, const float* __restrict__ w1,
                            const float* __restrict__ w2, const float* __restrict__ w3) {
    if (blockIdx.x < 256) {
        int i = blockIdx.x * 256 + threadIdx.x;
        int sel = i >> 14;
        const float* w = (sel == 0) ? w0 : (sel == 1) ? w1 : (sel == 2) ? w2 : w3;
        float4 v = ((const float4*)w)[i & 16383];
        uint2 u;
        u.x = packh2(v.x, v.y);
        u.y = packh2(v.z, v.w);
        ((uint2*)g_Wh)[i] = u;
        return;
    }
    int blk = blockIdx.x - 256;
    int bg = blk >> 3, slice = blk & 7;
    int b = bg / Gg, g = bg % Gg;
    const float4* xp = (const float4*)(x + ((size_t)b * Cc + g * CPG) * Nn)
                     + slice * (CPG * Nn / 4 / 8);
    const int n4 = CPG * Nn / 4 / 8;

    float s = 0.f, ss = 0.f;
    for (int i = threadIdx.x; i < n4; i += 256) {
        float4 v = xp[i];
        s  += v.x + v.y + v.z + v.w;
        ss += v.x * v.x + v.y * v.y + v.z * v.z + v.w * v.w;
    }
    __shared__ float rs[8], rss[8];
    #pragma unroll
    for (int off = 16; off; off >>= 1) {
        s  += __shfl_down_sync(0xffffffffu, s, off);
        ss += __shfl_down_sync(0xffffffffu, ss, off);
    }
    int lane = threadIdx.x & 31, wid = threadIdx.x >> 5;
    if (lane == 0) { rs[wid] = s; rss[wid] = ss; }
    __syncthreads();
    if (threadIdx.x < 8) {
        s = rs[threadIdx.x]; ss = rss[threadIdx.x];
        #pragma unroll
        for (int off = 4; off; off >>= 1) {
            s  += __shfl_down_sync(0xffu, s, off);
            ss += __shfl_down_sync(0xffu, ss, off);
        }
        if (threadIdx.x == 0) {
            g_part[(bg * 8 + slice) * 2 + 0] = s;
            g_part[(bg * 8 + slice) * 2 + 1] = ss;
        }
    }
}

// ---------------------------------------------------------------------------
// Kernel 1b: finalize
// ---------------------------------------------------------------------------
__global__ void gn_fin_kernel(const float* __restrict__ w,
                              const float* __restrict__ bias) {
    int t = threadIdx.x;
    int c = t & 255;
    int bg = t >> 5;
    float s = 0.f, ss = 0.f;
    #pragma unroll
    for (int i = 0; i < 8; i++) {
        s  += g_part[(bg * 8 + i) * 2 + 0];
        ss += g_part[(bg * 8 + i) * 2 + 1];
    }
    const float inv = 1.f / (float)(CPG * Nn);
    float mu = s * inv;
    float var = ss * inv - mu * mu;
    float rstd = rsqrtf(var + EPSv);
    float sc = rstd * w[c];
    g_scale[t] = sc;
    g_shift[t] = bias[c] - mu * sc;
}

// ---------------------------------------------------------------------------
// Kernel 3: stacked QKV GEMM with FUSED GroupNorm normalize.
// B tile: x fp32 -> regs -> scale/shift -> fp16 -> STS (prefetched LDG).
// A tile: fp16 weights via cp.async double-buffer.
// BM=128 BN=128 BK=32.
// ---------------------------------------------------------------------------
__global__ void __launch_bounds__(256)
gemm_qkv(const float* __restrict__ x, const __half* __restrict__ Wp,
         const float* __restrict__ bq, const float* __restrict__ bk,
         const float* __restrict__ bv) {
    __shared__ __align__(16) __half sA[2][128][40];
    __shared__ __align__(16) __half sB[2][32][136];

    int bz = blockIdx.z;
    const float* X = x + (size_t)bz * Cc * Nn;
    int n0 = blockIdx.x * 128;
    int mg = blockIdx.y * 128;
    int which = mg >> 8;
    int m0 = mg & 255;
    int tid = threadIdx.x, lane = tid & 31, wid = tid >> 5;
    int wm = wid & 1, wn = wid >> 1;
    int g = lane >> 2, tg = lane & 3;
    int r7 = lane & 7, sel = lane >> 3, r15 = lane & 15, hi8 = lane >> 4;

    float c[4][4][4] = {};

    // B prefetch registers: this thread covers row (tid>>3), 16 cols at (tid&7)*16
    int brow = tid >> 3, bcs = (tid & 7) << 4;
    float vb[16];

    auto issueA = [&](int kt, int buf) {
        int k0 = kt * 32;
        #pragma unroll
        for (int i = 0; i < 2; i++) {
            int idx = tid + i * 256;
            int arow = idx >> 2, acol = (idx & 3) << 3;
            cp16(smem_u32(&sA[buf][arow][acol]),
                 Wp + (size_t)(mg + arow) * Cc + k0 + acol);
        }
    };
    auto loadB = [&](int kt) {
        int k0 = kt * 32;
        const float* src = X + (size_t)(k0 + brow) * Nn + n0 + bcs;
        float s = g_scale[bz * Cc + k0 + brow];
        float sh = g_shift[bz * Cc + k0 + brow];
        #pragma unroll
        for (int i = 0; i < 4; i++) {
            float4 v = *(const float4*)(src + 4 * i);
            vb[4 * i + 0] = fmaf(v.x, s, sh);
            vb[4 * i + 1] = fmaf(v.y, s, sh);
            vb[4 * i + 2] = fmaf(v.z, s, sh);
            vb[4 * i + 3] = fmaf(v.w, s, sh);
        }
    };
    auto stsB = [&](int buf) {
        uint32_t h[8];
        #pragma unroll
        for (int i = 0; i < 8; i++)
            h[i] = packh2(vb[2 * i], vb[2 * i + 1]);
        *(uint4*)&sB[buf][brow][bcs]     = make_uint4(h[0], h[1], h[2], h[3]);
        *(uint4*)&sB[buf][brow][bcs + 8] = make_uint4(h[4], h[5], h[6], h[7]);
    };

    issueA(0, 0); CP_COMMIT();
    loadB(0);

    for (int kt = 0; kt < 8; kt++) {
        int cur = kt & 1;
        stsB(cur);
        if (kt + 1 < 8) { issueA(kt + 1, cur ^ 1); CP_COMMIT(); CP_WAIT1(); }
        else            { CP_WAIT0(); }
        __syncthreads();
        if (kt + 1 < 8) loadB(kt + 1);   // LDGs overlap compute

        #pragma unroll
        for (int ks = 0; ks < 2; ks++) {
            uint32_t a[4][4], bf[2][4];
            #pragma unroll
            for (int mt = 0; mt < 4; mt++)
                ldsm_x4(a[mt],
                        smem_u32(&sA[cur][wm * 64 + mt * 16 + (sel & 1) * 8 + r7]
                                        [ks * 16 + (sel >> 1) * 8]));
            #pragma unroll
            for (int jp = 0; jp < 2; jp++)
                ldsm_x4t(bf[jp],
                         smem_u32(&sB[cur][ks * 16 + r15][wn * 32 + jp * 16 + hi8 * 8]));
            #pragma unroll
            for (int mt = 0; mt < 4; mt++)
                #pragma unroll
                for (int jp = 0; jp < 2; jp++) {
                    mma16816(c[mt][jp * 2 + 0], a[mt], bf[jp][0], bf[jp][1]);
                    mma16816(c[mt][jp * 2 + 1], a[mt], bf[jp][2], bf[jp][3]);
                }
        }
        __syncthreads();
    }

    __half* outp = ((which == 0) ? g_Qh : (which == 1) ? g_Kh : g_Vh)
                 + (size_t)bz * Cc * Nn;
    const float* bp = (which == 0) ? bq : (which == 1) ? bk : bv;
    #pragma unroll
    for (int mt = 0; mt < 4; mt++) {
        int m = m0 + wm * 64 + mt * 16 + g;
        float b0 = bp[m], b1 = bp[m + 8];
        #pragma unroll
        for (int jt = 0; jt < 4; jt++) {
            int n = n0 + wn * 32 + jt * 8 + 2 * tg;
            *(__half2*)(outp + (size_t)m * Nn + n) =
                __floats2half2_rn(c[mt][jt][0] + b0, c[mt][jt][1] + b0);
            *(__half2*)(outp + (size_t)(m + 8) * Nn + n) =
                __floats2half2_rn(c[mt][jt][2] + b1, c[mt][jt][3] + b1);
        }
    }
}

// ---------------------------------------------------------------------------
// Kernel 5: output projection GEMM + residual, fp32 out.
// ---------------------------------------------------------------------------
__global__ void __launch_bounds__(256)
gemm_o(const __half* __restrict__ Wp, const float* __restrict__ bias,
       const float* __restrict__ resid, float* __restrict__ Out) {
    __shared__ __align__(16) __half sA[2][128][40];
    __shared__ __align__(16) __half sB[2][32][136];

    int bz = blockIdx.z;
    const __half* X = g_AOh + (size_t)bz * Cc * Nn;
    int n0 = blockIdx.x * 128, m0 = blockIdx.y * 128;
    int tid = threadIdx.x, lane = tid & 31, wid = tid >> 5;
    int wm = wid & 1, wn = wid >> 1;
    int g = lane >> 2, tg = lane & 3;
    int r7 = lane & 7, sel = lane >> 3, r15 = lane & 15, hi8 = lane >> 4;

    float c[4][4][4] = {};

    auto issue = [&](int kt, int buf) {
        int k0 = kt * 32;
        #pragma unroll
        for (int i = 0; i < 2; i++) {
            int idx = tid + i * 256;
            int arow = idx >> 2, acol = (idx & 3) << 3;
            cp16(smem_u32(&sA[buf][arow][acol]),
                 Wp + (size_t)(m0 + arow) * Cc + k0 + acol);
            int brow = idx >> 4, bcc = (idx & 15) << 3;
            cp16(smem_u32(&sB[buf][brow & 31][bcc]),
                 X + (size_t)(k0 + (brow & 31)) * Nn + n0 + bcc);
        }
    };

    issue(0, 0); CP_COMMIT();

    for (int kt = 0; kt < 8; kt++) {
        int cur = kt & 1;
        if (kt + 1 < 8) { issue(kt + 1, cur ^ 1); CP_COMMIT(); CP_WAIT1(); }
        else            { CP_WAIT0(); }
        __syncthreads();

        #pragma unroll
        for (int ks = 0; ks < 2; ks++) {
            uint32_t a[4][4], bf[2][4];
            #pragma unroll
            for (int mt = 0; mt < 4; mt++)
                ldsm_x4(a[mt],
                        smem_u32(&sA[cur][wm * 64 + mt * 16 + (sel & 1) * 8 + r7]
                                        [ks * 16 + (sel >> 1) * 8]));
            #pragma unroll
            for (int jp = 0; jp < 2; jp++)
                ldsm_x4t(bf[jp],
                         smem_u32(&sB[cur][ks * 16 + r15][wn * 32 + jp * 16 + hi8 * 8]));
            #pragma unroll
            for (int mt = 0; mt < 4; mt++)
                #pragma unroll
                for (int jp = 0; jp < 2; jp++) {
                    mma16816(c[mt][jp * 2 + 0], a[mt], bf[jp][0], bf[jp][1]);
                    mma16816(c[mt][jp * 2 + 1], a[mt], bf[jp][2], bf[jp][3]);
                }
        }
        __syncthreads();
    }

    #pragma unroll
    for (int mt = 0; mt < 4; mt++) {
        int m = m0 + wm * 64 + mt * 16 + g;
        float b0 = bias[m], b1 = bias[m + 8];
        #pragma unroll
        for (int jt = 0; jt < 4; jt++) {
            int n = n0 + wn * 32 + jt * 8 + 2 * tg;
            size_t o0 = ((size_t)bz * Cc + m) * Nn + n;
            size_t o1 = ((size_t)bz * Cc + m + 8) * Nn + n;
            float2 r0 = *(const float2*)(resid + o0);
            float2 r1 = *(const float2*)(resid + o1);
            *(float2*)(Out + o0) = make_float2(c[mt][jt][0] + b0 + r0.x,
                                               c[mt][jt][1] + b0 + r0.y);
            *(float2*)(Out + o1) = make_float2(c[mt][jt][2] + b1 + r1.x,
                                               c[mt][jt][3] + b1 + r1.y);
        }
    }
}

// ---------------------------------------------------------------------------
// Kernel 4: HMMA flash attention — EXACT R14 structure (proven best).
// 512 q/block, grid 128 = 1 balanced wave, Bc=128, 4-stage ring, 1 barrier/iter,
// rowsums via MMA with B=ones (R11/R15 falsified the fma-pipe variant).
// ---------------------------------------------------------------------------
extern __shared__ __half s_attn[];

__global__ void __launch_bounds__(256, 1)
attn_kernel() {
    __half* sK = s_attn + SK_OFF;   // [4][32][136]
    __half* sV = s_attn + SV_OFF;   // [4][32][136]
    __half* sQ = s_attn + SQ_OFF;   // [32][520]

    int tid = threadIdx.x, lane = tid & 31, wid = tid >> 5;
    int b = blockIdx.z, h = blockIdx.y;
    int q0 = blockIdx.x * 512;
    size_t base = ((size_t)b * Cc + h * 32) * Nn;
    const __half* Qg = g_Qh + base;
    const __half* Kg = g_Kh + base;
    const __half* Vg = g_Vh + base;
    int g = lane >> 2, tg = lane & 3;
    int r7 = lane & 7, sel = lane >> 3, r15 = lane & 15, hi8 = lane >> 4;

    auto kv_off = [](int buf, int row, int col) {
        return buf * KV_BUF + row * 136 + col;
    };
    auto issue = [&](int t, int buf) {
        int row = tid >> 3;
        #pragma unroll
        for (int i = 0; i < 2; i++) {
            int cc = ((tid & 7) << 3) + i * 64;
            size_t off = (size_t)row * Nn + t * 128 + cc;
            cp16(smem_u32(sK + kv_off(buf, row, cc)), Kg + off);
            cp16(smem_u32(sV + kv_off(buf, row, cc)), Vg + off);
        }
    };

    issue(0, 0); CP_COMMIT();
    issue(1, 1); CP_COMMIT();

    #pragma unroll
    for (int i = 0; i < 8; i++) {
        int idx = tid + i * 256;
        int row = idx >> 6, cc = (idx & 63) << 3;
        *(uint4*)(sQ + row * SQ_STRIDE + cc) =
            *(const uint4*)(Qg + (size_t)row * Nn + q0 + cc);
    }
    __syncthreads();
    uint32_t qa[4][2][4];
    const __half2 cs2 = __float2half2_rn(CEXP);
    #pragma unroll
    for (int mt = 0; mt < 4; mt++)
        #pragma unroll
        for (int s = 0; s < 2; s++) {
            ldsm_x4t(qa[mt][s],
                     smem_u32(sQ + (s * 16 + (sel >> 1) * 8 + r7) * SQ_STRIDE
                                 + wid * 64 + mt * 16 + (sel & 1) * 8));
            #pragma unroll
            for (int i = 0; i < 4; i++) {
                __half2 t2 = __hmul2(*(__half2*)&qa[mt][s][i], cs2);
                qa[mt][s][i] = *(uint32_t*)&t2;
            }
        }

    float oc[4][4][4] = {};
    float rc[4][4] = {};
    const uint32_t ONES = 0x3C003C00u;
    const int NT = Nn / 128;   // 32

    for (int t = 0; t < NT; t++) {
        int cur = t & 3;
        if (t + 2 < NT) { issue(t + 2, (t + 2) & 3); CP_COMMIT(); CP_WAIT2(); }
        else if (t + 1 < NT) { CP_WAIT1(); }
        else                 { CP_WAIT0(); }
        __syncthreads();   // the ONLY barrier in the iteration

        #pragma unroll
        for (int jp = 0; jp < 8; jp++) {
            uint32_t kf[2][4];
            #pragma unroll
            for (int s = 0; s < 2; s++)
                ldsm_x4t(kf[s], smem_u32(sK + kv_off(cur, s * 16 + r15,
                                                     jp * 16 + hi8 * 8)));
            uint32_t pa[4][4];
            #pragma unroll
            for (int mt = 0; mt < 4; mt++)
                #pragma unroll
                for (int j2 = 0; j2 < 2; j2++) {
                    float sc[4] = {0.f, 0.f, 0.f, 0.f};
                    mma16816(sc, qa[mt][0], kf[0][j2 * 2], kf[0][j2 * 2 + 1]);
                    mma16816(sc, qa[mt][1], kf[1][j2 * 2], kf[1][j2 * 2 + 1]);
                    pa[mt][j2 * 2 + 0] = exp2h2(sc[0], sc[1]);
                    pa[mt][j2 * 2 + 1] = exp2h2(sc[2], sc[3]);
                }
            #pragma unroll
            for (int mt = 0; mt < 4; mt++)
                mma16816(rc[mt], pa[mt], ONES, ONES);
            #pragma unroll
            for (int dnp = 0; dnp < 2; dnp++) {
                uint32_t vf[4];
                ldsm_x4(vf, smem_u32(sV + kv_off(cur, dnp * 16 + hi8 * 8 + r7,
                                                 jp * 16 + ((lane >> 3) & 1) * 8)));
                #pragma unroll
                for (int mt = 0; mt < 4; mt++) {
                    mma16816(oc[mt][dnp * 2],     pa[mt], vf[0], vf[1]);
                    mma16816(oc[mt][dnp * 2 + 1], pa[mt], vf[2], vf[3]);
                }
            }
        }
    }

    __syncthreads();
    #pragma unroll
    for (int mt = 0; mt < 4; mt++) {
        float inv0 = 1.f / rc[mt][0], inv1 = 1.f / rc[mt][2];
        int qc = wid * 64 + mt * 16;
        #pragma unroll
        for (int dn = 0; dn < 4; dn++) {
            int d0 = dn * 8 + 2 * tg;
            sQ[d0 * SQ_STRIDE + qc + g]           = __float2half(oc[mt][dn][0] * inv0);
            sQ[(d0 + 1) * SQ_STRIDE + qc + g]     = __float2half(oc[mt][dn][1] * inv0);
            sQ[d0 * SQ_STRIDE + qc + g + 8]       = __float2half(oc[mt][dn][2] * inv1);
            sQ[(d0 + 1) * SQ_STRIDE + qc + g + 8] = __float2half(oc[mt][dn][3] * inv1);
        }
    }
    __syncthreads();
    __half* AO = g_AOh + base;
    #pragma unroll
    for (int i = 0; i < 8; i++) {
        int idx = tid + i * 256;
        int row = idx >> 6, cc = (idx & 63) << 3;
        *(uint4*)(AO + (size_t)row * Nn + q0 + cc) =
            *(uint4*)(sQ + row * SQ_STRIDE + cc);
    }
}

// ---------------------------------------------------------------------------
// Launch
// ---------------------------------------------------------------------------
extern "C" void kernel_launch(void* const* d_in, const int* in_sizes, int n_in,
                              void* d_out, int out_size) {
    const float* x    = (const float*)d_in[0];
    const float* gn_w = (const float*)d_in[1];
    const float* gn_b = (const float*)d_in[2];
    const float* wq   = (const float*)d_in[3];
    const float* bq   = (const float*)d_in[4];
    const float* wk   = (const float*)d_in[5];
    const float* bk   = (const float*)d_in[6];
    const float* wv   = (const float*)d_in[7];
    const float* bv   = (const float*)d_in[8];
    const float* wo   = (const float*)d_in[9];
    const float* bo   = (const float*)d_in[10];
    float* out = (float*)d_out;

    __half* wh;
    cudaGetSymbolAddress((void**)&wh, g_Wh);

    static bool attr_set = false;
    if (!attr_set) {
        cudaFuncSetAttribute(attn_kernel,
                             cudaFuncAttributeMaxDynamicSharedMemorySize,
                             ATTN_SMEM_BYTES);
        attr_set = true;
    }

    prep_kernel<<<384, 256>>>(x, wq, wk, wv, wo);
    gn_fin_kernel<<<1, 512>>>(gn_w, gn_b);

    gemm_qkv<<<dim3(Nn / 128, 6, Bsz), 256>>>(x, wh, bq, bk, bv);

    attn_kernel<<<dim3(Nn / 512, Hh, Bsz), 256, ATTN_SMEM_BYTES>>>();

    gemm_o<<<dim3(Nn / 128, Cc / 128, Bsz), 256>>>(wh + 3 * Cc * Cc, bo, x, out);
}